// round 9
// baseline (speedup 1.0000x reference)
#include <cuda_runtime.h>
#include <cuda_fp16.h>
#include <cstdint>

// ============================================================================
// out[b,l,d] = sum_{i,j} x0[b,i,d]*x1[b,j,d]*filters[i*64+j, l]
// B=2048, F1=F2=64, D=16, L=16.
//
// R9: dual-pipe. mma.sync on sm_100 is rate-capped at ~26 cyc/instr/SMSP
// (proven invariant over R4-R8), so offload i in [48,64) to the idle fma pipe
// via packed fma.rn.f32x2 (fp32-exact), staggered by warp parity so tensor
// and fma pipes run concurrently. HMMA keeps i in [0,48) (R7 structure).
// ============================================================================

// Pre-arranged W fragment image: [i(64)][kstep(4)][lane(32)] x 16B.
__device__ __align__(16) uint4 g_Wfrag[64 * 4 * 32];

__device__ __forceinline__ uint32_t pack_half2(float a, float b) {
    __half2 h = __floats2half2_rn(a, b);
    return *(uint32_t*)&h;
}

__device__ __forceinline__ uint32_t hmul2(uint32_t a, uint32_t b) {
    uint32_t d;
    asm("mul.rn.f16x2 %0, %1, %2;" : "=r"(d) : "r"(a), "r"(b));
    return d;
}

__device__ __forceinline__ void mma16816(float c[4], const uint4& a, const uint2& b) {
    asm volatile(
        "mma.sync.aligned.m16n8k16.row.col.f32.f16.f16.f32 "
        "{%0,%1,%2,%3}, {%4,%5,%6,%7}, {%8,%9}, {%0,%1,%2,%3};\n"
        : "+f"(c[0]), "+f"(c[1]), "+f"(c[2]), "+f"(c[3])
        : "r"(a.x), "r"(a.y), "r"(a.z), "r"(a.w), "r"(b.x), "r"(b.y));
}

// packed f32x2 helpers (scalar path)
__device__ __forceinline__ uint64_t dup2(float x) {
    uint64_t r;
    asm("mov.b64 %0, {%1, %1};" : "=l"(r) : "f"(x));
    return r;
}
__device__ __forceinline__ uint64_t fma2(uint64_t a, uint64_t b, uint64_t c) {
    uint64_t d;
    asm("fma.rn.f32x2 %0, %1, %2, %3;" : "=l"(d) : "l"(a), "l"(b), "l"(c));
    return d;
}

// ---------------------------------------------------------- prep kernel -----
__global__ void prep_w_kernel(const float* __restrict__ filters) {
    int idx  = blockIdx.x * 256 + threadIdx.x;    // 8192 total
    int i    = (idx >> 7) & 63;
    int t    = (idx >> 5) & 3;
    int lane = idx & 31;
    int gid = lane >> 2, q = lane & 3;
    int k0 = t * 16 + q * 2;
    int l0 = gid, l1 = gid + 8;

    float e[8];
    int ls[8] = {l0, l0, l1, l1, l0, l0, l1, l1};
    int ks[8] = {k0, k0 + 1, k0, k0 + 1, k0 + 8, k0 + 9, k0 + 8, k0 + 9};
    #pragma unroll
    for (int j = 0; j < 8; ++j)
        e[j] = filters[(i * 64 + ks[j]) * 16 + ls[j]];

    g_Wfrag[idx] = make_uint4(pack_half2(e[0], e[1]), pack_half2(e[2], e[3]),
                              pack_half2(e[4], e[5]), pack_half2(e[6], e[7]));
}

// ------------------------------------------------------------ main kernel ---
// SMEM: x0h (24KB, fp16-dup, i<48) | x0f (8KB, f32, i>=48) | x1r (32KB raw)
// post-mainloop overlays: wb (hmma partials) on x0h, wb2 (scalar) on x1r.
static constexpr int SM_X0H = 0;        // 48*128 u32
static constexpr int SM_X0F = 24576;    // 16*128 f32
static constexpr int SM_X1R = 32768;    // [bl][j][d] f32, persists
static constexpr int SM_WB  = 0;        // hmma partials (17.4KB)
static constexpr int SM_WB2 = 32768;    // scalar partials (32KB)
static constexpr int SMEM_TOTAL = 65536;

__global__ __launch_bounds__(256, 2) void fm_main_kernel(
    const float* __restrict__ x0g,
    const float* __restrict__ x1g,
    const float* __restrict__ filters,
    float* __restrict__ outg)
{
    extern __shared__ __align__(16) unsigned char smem[];
    uint32_t* x0h  = (uint32_t*)(smem + SM_X0H);
    float*    x0f  = (float*)(smem + SM_X0F);
    float*    x1r  = (float*)(smem + SM_X1R);
    float4*   x1r4 = (float4*)(smem + SM_X1R);
    float*    wb   = (float*)(smem + SM_WB);
    float*    wb2f = (float*)(smem + SM_WB2);

    int tid = threadIdx.x;
    int w = tid >> 5, lane = tid & 31;
    int gid = lane >> 2, q = lane & 3;
    int Q = w & 3;         // mc-quarter
    int h = w >> 2;        // i-half of the HMMA range [0,48)
    int bbase = blockIdx.x * 8;   // 8 b's -> 128 (b,d) rows per CTA

    // ---- stage x1 (persists in x1r), then build register B fragments ----
    const float4* x1s = (const float4*)(x1g + (size_t)bbase * 1024);
    for (int e = tid; e < 2048; e += 256) x1r4[e] = x1s[e];
    __syncthreads();

    uint2 Bf[4][4];
    #pragma unroll
    for (int mcl = 0; mcl < 4; ++mcl) {
        int r = (Q * 4 + mcl) * 8 + gid;
        int bl = r >> 4, d = r & 15;
        const float* base = x1r + bl * 1024 + d;
        #pragma unroll
        for (int t = 0; t < 4; ++t) {
            int k0 = t * 16 + q * 2;
            Bf[mcl][t] = make_uint2(
                pack_half2(base[k0 * 16], base[(k0 + 1) * 16]),
                pack_half2(base[(k0 + 8) * 16], base[(k0 + 9) * 16]));
        }
    }

    // ---- build x0h (fp16-dup, i<48) and x0f (f32, i>=48) from global ----
    for (int e = tid; e < 8192; e += 256) {
        int i = e >> 7, m = e & 127;
        float v = x0g[(size_t)(bbase + (m >> 4)) * 1024 + i * 16 + (m & 15)];
        if (i < 48) {
            __half hh = __float2half(v);
            x0h[e] = (uint32_t)(*(unsigned short*)&hh) * 0x00010001u;
        } else {
            x0f[(i - 48) * 128 + m] = v;
        }
    }
    __syncthreads();

    // ---- accumulators for both paths ----
    float acc[4][4];
    #pragma unroll
    for (int mcl = 0; mcl < 4; ++mcl)
        #pragma unroll
        for (int r = 0; r < 4; ++r) acc[mcl][r] = 0.0f;

    uint64_t a2[4][4];
    #pragma unroll
    for (int mi = 0; mi < 4; ++mi)
        #pragma unroll
        for (int lp = 0; lp < 4; ++lp) a2[mi][lp] = 0ull;

    // ---- HMMA path: i in [h*24, h*24+24) ----
    auto run_hmma = [&]() {
        const uint4* wp = g_Wfrag + lane;
        int i0 = h * 24;
        uint4 Wc[4], Wn[4];
        #pragma unroll
        for (int t = 0; t < 4; ++t) Wc[t] = wp[(i0 * 4 + t) * 32];
        for (int il = 0; il < 24; ++il) {
            int i = i0 + il;
            if (il < 23) {
                #pragma unroll
                for (int t = 0; t < 4; ++t) Wn[t] = wp[((i + 1) * 4 + t) * 32];
            }
            #pragma unroll
            for (int mcl = 0; mcl < 4; ++mcl) {
                uint32_t xh = x0h[i * 128 + (Q * 4 + mcl) * 8 + gid];
                #pragma unroll
                for (int t = 0; t < 4; ++t) {
                    uint2 bs = make_uint2(hmul2(Bf[mcl][t].x, xh),
                                          hmul2(Bf[mcl][t].y, xh));
                    mma16816(acc[mcl], Wc[t], bs);
                }
            }
            #pragma unroll
            for (int t = 0; t < 4; ++t) Wc[t] = Wn[t];
        }
    };

    // ---- scalar f32x2 path: i in [48,64), thread = (mg, lh, ih) ----
    // thread covers m = w*16 + mg*4 .. +3, l = lh*8 .. +7, i = 48+ih*4 .. +3
    auto run_scalar = [&]() {
        int mg = lane & 3, lh = (lane >> 2) & 1, ih = lane >> 3;
        const float* x1b = x1r + w * 1024 + mg * 4;
        #pragma unroll
        for (int ii = 0; ii < 4; ++ii) {
            int i = 48 + ih * 4 + ii;
            float4 x0q = *(const float4*)&x0f[(i - 48) * 128 + w * 16 + mg * 4];
            const float* fb = filters + (size_t)(i * 64) * 16 + lh * 8;
            #pragma unroll 4
            for (int j = 0; j < 64; ++j) {
                float4 x1q = *(const float4*)&x1b[j * 16];
                ulonglong2 wa = *(const ulonglong2*)(fb + j * 16);
                ulonglong2 wc = *(const ulonglong2*)(fb + j * 16 + 4);
                uint64_t p0 = dup2(x0q.x * x1q.x);
                uint64_t p1 = dup2(x0q.y * x1q.y);
                uint64_t p2 = dup2(x0q.z * x1q.z);
                uint64_t p3 = dup2(x0q.w * x1q.w);
                a2[0][0] = fma2(wa.x, p0, a2[0][0]);
                a2[0][1] = fma2(wa.y, p0, a2[0][1]);
                a2[0][2] = fma2(wc.x, p0, a2[0][2]);
                a2[0][3] = fma2(wc.y, p0, a2[0][3]);
                a2[1][0] = fma2(wa.x, p1, a2[1][0]);
                a2[1][1] = fma2(wa.y, p1, a2[1][1]);
                a2[1][2] = fma2(wc.x, p1, a2[1][2]);
                a2[1][3] = fma2(wc.y, p1, a2[1][3]);
                a2[2][0] = fma2(wa.x, p2, a2[2][0]);
                a2[2][1] = fma2(wa.y, p2, a2[2][1]);
                a2[2][2] = fma2(wc.x, p2, a2[2][2]);
                a2[2][3] = fma2(wc.y, p2, a2[2][3]);
                a2[3][0] = fma2(wa.x, p3, a2[3][0]);
                a2[3][1] = fma2(wa.y, p3, a2[3][1]);
                a2[3][2] = fma2(wc.x, p3, a2[3][2]);
                a2[3][3] = fma2(wc.y, p3, a2[3][3]);
            }
        }
    };

    // stagger by warp parity so tensor + fma pipes run concurrently
    if (w & 1) { run_scalar(); run_hmma(); }
    else       { run_hmma(); run_scalar(); }

    __syncthreads();   // all reads of x0h/x1r done; safe to overlay wb/wb2

    // ---- HMMA partial writeback (R7 scheme, pad 136 kills conflicts) ----
    #pragma unroll
    for (int mcl = 0; mcl < 4; ++mcl) {
        float* bptr = wb + (w * 4 + mcl) * 136;
        *(float2*)&bptr[gid * 8 + 2 * q]       = make_float2(acc[mcl][0], acc[mcl][1]);
        *(float2*)&bptr[(gid + 8) * 8 + 2 * q] = make_float2(acc[mcl][2], acc[mcl][3]);
    }
    // ---- scalar partial writeback: wb2[(ih*8+w)*256 + m_local*16 + l] ----
    {
        int mg = lane & 3, lh = (lane >> 2) & 1, ih = lane >> 3;
        #pragma unroll
        for (int mi = 0; mi < 4; ++mi) {
            float* base = wb2f + (ih * 8 + w) * 256 + (mg * 4 + mi) * 16 + lh * 8;
            #pragma unroll
            for (int lp = 0; lp < 4; ++lp)
                *(uint64_t*)&base[lp * 2] = a2[mi][lp];
        }
    }
    __syncthreads();

    // ---- final reduce: 2 hmma halves + 4 scalar ih slices; coalesced store --
    for (int o = tid; o < 2048; o += 256) {
        int l = o >> 7, m = o & 127;
        int Q2 = m >> 5, mcl = (m >> 3) & 3, mloc = m & 7;
        int off = (Q2 * 4 + mcl) * 136 + l * 8 + mloc;
        float s = wb[off] + wb[off + 16 * 136];
        int b2 = (m >> 4) * 256 + (m & 15) * 16 + l;
        s += wb2f[b2] + wb2f[b2 + 2048] + wb2f[b2 + 4096] + wb2f[b2 + 6144];
        int bl = m >> 4, d = m & 15;
        outg[(size_t)(bbase + bl) * 256 + l * 16 + d] = s;
    }
}

// ------------------------------------------------------------------ launch --
extern "C" void kernel_launch(void* const* d_in, const int* in_sizes, int n_in,
                              void* d_out, int out_size) {
    const float* x0 = (const float*)d_in[0];
    const float* x1 = (const float*)d_in[1];
    const float* filters = (const float*)d_in[2];
    float* out = (float*)d_out;

    cudaFuncSetAttribute(fm_main_kernel,
                         cudaFuncAttributeMaxDynamicSharedMemorySize, SMEM_TOTAL);

    prep_w_kernel<<<32, 256>>>(filters);
    fm_main_kernel<<<256, 256, SMEM_TOTAL>>>(x0, x1, filters, out);
}

// round 10
// speedup vs baseline: 1.0301x; 1.0301x over previous
#include <cuda_runtime.h>
#include <cuda_fp16.h>
#include <cstdint>

// ============================================================================
// out[b,l,d] = sum_{i,j} x0[b,i,d]*x1[b,j,d]*filters[i*64+j, l]
// B=2048, F1=F2=64, D=16, L=16.
//
// R10: disciplined dual-pipe. mma.sync capped ~26cyc/instr/SMSP (R4-R8), so
// offload i in [52,64) to the fma pipe with packed fma.rn.f32x2:
//  - scalar thread state = 8 regs (4 f32x2 accs), no spills
//  - W slice staged to SMEM f32 (broadcast LDS.128), x1 coalesced LDS
//  - warp-parity stagger: 2 warps/SMSP per pipe (2 warps saturate tensor, R4)
// HMMA path (i<52) = R7 structure unchanged.
// ============================================================================

static constexpr int NSI = 12;   // scalar i's: [52, 64)
static constexpr int NHI = 52;   // hmma i's:   [0, 52), 26 per h-half

// Pre-arranged W fragment image: [i(64)][kstep(4)][lane(32)] x 16B.
__device__ __align__(16) uint4 g_Wfrag[64 * 4 * 32];

__device__ __forceinline__ uint32_t pack_half2(float a, float b) {
    __half2 h = __floats2half2_rn(a, b);
    return *(uint32_t*)&h;
}
__device__ __forceinline__ uint32_t hmul2(uint32_t a, uint32_t b) {
    uint32_t d;
    asm("mul.rn.f16x2 %0, %1, %2;" : "=r"(d) : "r"(a), "r"(b));
    return d;
}
__device__ __forceinline__ void mma16816(float c[4], const uint4& a, const uint2& b) {
    asm volatile(
        "mma.sync.aligned.m16n8k16.row.col.f32.f16.f16.f32 "
        "{%0,%1,%2,%3}, {%4,%5,%6,%7}, {%8,%9}, {%0,%1,%2,%3};\n"
        : "+f"(c[0]), "+f"(c[1]), "+f"(c[2]), "+f"(c[3])
        : "r"(a.x), "r"(a.y), "r"(a.z), "r"(a.w), "r"(b.x), "r"(b.y));
}
__device__ __forceinline__ uint64_t dup2(float x) {
    uint64_t r;
    asm("mov.b64 %0, {%1, %1};" : "=l"(r) : "f"(x));
    return r;
}
__device__ __forceinline__ uint64_t fma2(uint64_t a, uint64_t b, uint64_t c) {
    uint64_t d;
    asm("fma.rn.f32x2 %0, %1, %2, %3;" : "=l"(d) : "l"(a), "l"(b), "l"(c));
    return d;
}

// ---------------------------------------------------------- prep kernel -----
__global__ void prep_w_kernel(const float* __restrict__ filters) {
    int idx  = blockIdx.x * 256 + threadIdx.x;    // 8192 total
    int i    = (idx >> 7) & 63;
    int t    = (idx >> 5) & 3;
    int lane = idx & 31;
    int gid = lane >> 2, q = lane & 3;
    int k0 = t * 16 + q * 2;
    int l0 = gid, l1 = gid + 8;

    float e[8];
    int ls[8] = {l0, l0, l1, l1, l0, l0, l1, l1};
    int ks[8] = {k0, k0 + 1, k0, k0 + 1, k0 + 8, k0 + 9, k0 + 8, k0 + 9};
    #pragma unroll
    for (int j = 0; j < 8; ++j)
        e[j] = filters[(i * 64 + ks[j]) * 16 + ls[j]];

    g_Wfrag[idx] = make_uint4(pack_half2(e[0], e[1]), pack_half2(e[2], e[3]),
                              pack_half2(e[4], e[5]), pack_half2(e[6], e[7]));
}

// ------------------------------------------------------------ main kernel ---
// SMEM map (112KB): x0h 26KB | x0f 6KB | x1r 32KB | Ws 48KB
// post-mainloop overlays: wb (hmma partials, 17.4KB) on x0h; wb2 (8KB) on Ws.
static constexpr int SM_X0H = 0;        // 52*128 u32 (fp16-dup x0, i<52)
static constexpr int SM_X0F = 26624;    // 12*128 f32 (x0, i>=52)
static constexpr int SM_X1R = 32768;    // 8192 f32 raw x1 [bl][j][d]
static constexpr int SM_WS  = 65536;    // 12*64*16 f32 W slice (i>=52)
static constexpr int SM_WB  = 0;        // hmma partials overlay
static constexpr int SM_WB2 = 65536;    // scalar partials overlay (128*16 f32)
static constexpr int SMEM_TOTAL = 65536 + 49152;   // 114688

__global__ __launch_bounds__(256, 2) void fm_main_kernel(
    const float* __restrict__ x0g,
    const float* __restrict__ x1g,
    const float* __restrict__ filters,
    float* __restrict__ outg)
{
    extern __shared__ __align__(16) unsigned char smem[];
    uint32_t* x0h  = (uint32_t*)(smem + SM_X0H);
    float*    x0f  = (float*)(smem + SM_X0F);
    float*    x1r  = (float*)(smem + SM_X1R);
    float4*   x1r4 = (float4*)(smem + SM_X1R);
    float*    ws   = (float*)(smem + SM_WS);
    float*    wb   = (float*)(smem + SM_WB);
    float*    wb2  = (float*)(smem + SM_WB2);

    int tid = threadIdx.x;
    int w = tid >> 5, lane = tid & 31;
    int gid = lane >> 2, q = lane & 3;
    int Q = w & 3;         // mc-quarter
    int h = w >> 2;        // i-half of [0,52)
    int bbase = blockIdx.x * 8;

    // ---- stage x1 raw + Ws (contiguous filters block, i>=52) ----
    const float4* x1s = (const float4*)(x1g + (size_t)bbase * 1024);
    for (int e = tid; e < 2048; e += 256) x1r4[e] = x1s[e];
    const float4* fsrc = (const float4*)(filters + NHI * 64 * 16);
    float4* wsd = (float4*)ws;
    for (int e = tid; e < NSI * 256; e += 256) wsd[e] = fsrc[e];
    __syncthreads();

    // ---- register B fragments from x1r ----
    uint2 Bf[4][4];
    #pragma unroll
    for (int mcl = 0; mcl < 4; ++mcl) {
        int r = (Q * 4 + mcl) * 8 + gid;
        int bl = r >> 4, d = r & 15;
        const float* base = x1r + bl * 1024 + d;
        #pragma unroll
        for (int t = 0; t < 4; ++t) {
            int k0 = t * 16 + q * 2;
            Bf[mcl][t] = make_uint2(
                pack_half2(base[k0 * 16], base[(k0 + 1) * 16]),
                pack_half2(base[(k0 + 8) * 16], base[(k0 + 9) * 16]));
        }
    }

    // ---- stage x0: fp16-dup (i<52) and f32 (i>=52) ----
    for (int e = tid; e < 8192; e += 256) {
        int i = e >> 7, m = e & 127;
        float v = x0g[(size_t)(bbase + (m >> 4)) * 1024 + i * 16 + (m & 15)];
        if (i < NHI) {
            __half hh = __float2half(v);
            x0h[e] = (uint32_t)(*(unsigned short*)&hh) * 0x00010001u;
        } else {
            x0f[(i - NHI) * 128 + m] = v;
        }
    }
    __syncthreads();

    // ---- accumulators ----
    float acc[4][4];
    #pragma unroll
    for (int mcl = 0; mcl < 4; ++mcl)
        #pragma unroll
        for (int r = 0; r < 4; ++r) acc[mcl][r] = 0.0f;
    uint64_t a2[4] = {0ull, 0ull, 0ull, 0ull};

    // ---- HMMA path: 26 i's ----
    auto run_hmma = [&]() {
        const uint4* wp = g_Wfrag + lane;
        int i0 = h * 26;
        uint4 Wc[4], Wn[4];
        #pragma unroll
        for (int t = 0; t < 4; ++t) Wc[t] = wp[(i0 * 4 + t) * 32];
        for (int il = 0; il < 26; ++il) {
            int i = i0 + il;
            if (il < 25) {
                #pragma unroll
                for (int t = 0; t < 4; ++t) Wn[t] = wp[((i + 1) * 4 + t) * 32];
            }
            #pragma unroll
            for (int mcl = 0; mcl < 4; ++mcl) {
                uint32_t xh = x0h[i * 128 + (Q * 4 + mcl) * 8 + gid];
                #pragma unroll
                for (int t = 0; t < 4; ++t) {
                    uint2 bs = make_uint2(hmul2(Bf[mcl][t].x, xh),
                                          hmul2(Bf[mcl][t].y, xh));
                    mma16816(acc[mcl], Wc[t], bs);
                }
            }
            #pragma unroll
            for (int t = 0; t < 4; ++t) Wc[t] = Wn[t];
        }
    };

    // ---- scalar f32x2 path: thread = (m = tid>>1, lh = tid&1), 8 l's ----
    auto run_scalar = [&]() {
        int sm_ = tid >> 1;
        int lh = tid & 1;
        const float* x1b = x1r + (sm_ >> 4) * 1024 + (sm_ & 15);
        const float* wsb = ws + lh * 8;
        for (int ii = 0; ii < NSI; ++ii) {
            float x0c = x0f[ii * 128 + sm_];
            const float* wrow = wsb + ii * 1024;
            #pragma unroll 4
            for (int j = 0; j < 64; ++j) {
                uint64_t pd = dup2(x0c * x1b[j * 16]);
                ulonglong2 w0 = *(const ulonglong2*)(wrow + j * 16);
                ulonglong2 w1 = *(const ulonglong2*)(wrow + j * 16 + 4);
                a2[0] = fma2(w0.x, pd, a2[0]);
                a2[1] = fma2(w0.y, pd, a2[1]);
                a2[2] = fma2(w1.x, pd, a2[2]);
                a2[3] = fma2(w1.y, pd, a2[3]);
            }
        }
    };

    // stagger so ~2 warps/SMSP feed each pipe at any time
    if (w & 1) { run_scalar(); run_hmma(); }
    else       { run_hmma(); run_scalar(); }

    __syncthreads();   // mainloop reads done; overlays safe

    // ---- HMMA partial writeback (pad 136) ----
    #pragma unroll
    for (int mcl = 0; mcl < 4; ++mcl) {
        float* bptr = wb + (w * 4 + mcl) * 136;
        *(float2*)&bptr[gid * 8 + 2 * q]       = make_float2(acc[mcl][0], acc[mcl][1]);
        *(float2*)&bptr[(gid + 8) * 8 + 2 * q] = make_float2(acc[mcl][2], acc[mcl][3]);
    }
    // ---- scalar partial writeback: wb2[m*16 + l] ----
    {
        int sm_ = tid >> 1, lh = tid & 1;
        uint64_t* dst = (uint64_t*)(wb2 + sm_ * 16 + lh * 8);
        dst[0] = a2[0]; dst[1] = a2[1]; dst[2] = a2[2]; dst[3] = a2[3];
    }
    __syncthreads();

    // ---- final reduce: 2 hmma halves + scalar; coalesced store ----
    for (int o = tid; o < 2048; o += 256) {
        int l = o >> 7, m = o & 127;
        int Q2 = m >> 5, mcl = (m >> 3) & 3, mloc = m & 7;
        int off = (Q2 * 4 + mcl) * 136 + l * 8 + mloc;
        float s = wb[off] + wb[off + 16 * 136] + wb2[m * 16 + l];
        int bl = m >> 4, d = m & 15;
        outg[(size_t)(bbase + bl) * 256 + l * 16 + d] = s;
    }
}

// ------------------------------------------------------------------ launch --
extern "C" void kernel_launch(void* const* d_in, const int* in_sizes, int n_in,
                              void* d_out, int out_size) {
    const float* x0 = (const float*)d_in[0];
    const float* x1 = (const float*)d_in[1];
    const float* filters = (const float*)d_in[2];
    float* out = (float*)d_out;

    cudaFuncSetAttribute(fm_main_kernel,
                         cudaFuncAttributeMaxDynamicSharedMemorySize, SMEM_TOTAL);

    prep_w_kernel<<<32, 256>>>(filters);
    fm_main_kernel<<<256, 256, SMEM_TOTAL>>>(x0, x1, filters, out);
}

// round 11
// speedup vs baseline: 1.5768x; 1.5308x over previous
#include <cuda_runtime.h>
#include <cuda_fp16.h>
#include <cstdint>

// ============================================================================
// out[b,l,d] = sum_{i,j} x0[b,i,d]*x1[b,j,d]*filters[i*64+j, l]
// B=2048, F1=F2=64, D=16, L=16.
//
// R11: (1) wave balance: grid=148, 1 CTA/SM, CTA = 13-14 b, uniform HMMA
//      issue count on every SM (clamped garbage chunks for nb=13).
//      (2) DEDICATED scalar warps: 12 warps/CTA -> per SMSP 2 HMMA + 1 scalar.
//      HMMA (R7 loop, i<56): 1568 HMMA/SMSP * 26cyc = 40.8K window.
//      Scalar (fp32 fma.f32x2, i in [56,64)): ~18K fma-pipe, hides inside.
// ============================================================================

static constexpr int NHI = 56;    // hmma i's [0,56); scalar [56,64)
static constexpr int MMAX = 224;  // max m rows per CTA (14 b)

// Pre-arranged W fragment image: [i(64)][kstep(4)][lane(32)] x 16B.
__device__ __align__(16) uint4 g_Wfrag[64 * 4 * 32];

__device__ __forceinline__ uint32_t pack_half2(float a, float b) {
    __half2 h = __floats2half2_rn(a, b);
    return *(uint32_t*)&h;
}
__device__ __forceinline__ uint32_t hmul2(uint32_t a, uint32_t b) {
    uint32_t d;
    asm("mul.rn.f16x2 %0, %1, %2;" : "=r"(d) : "r"(a), "r"(b));
    return d;
}
__device__ __forceinline__ void mma16816(float c[4], const uint4& a, const uint2& b) {
    asm volatile(
        "mma.sync.aligned.m16n8k16.row.col.f32.f16.f16.f32 "
        "{%0,%1,%2,%3}, {%4,%5,%6,%7}, {%8,%9}, {%0,%1,%2,%3};\n"
        : "+f"(c[0]), "+f"(c[1]), "+f"(c[2]), "+f"(c[3])
        : "r"(a.x), "r"(a.y), "r"(a.z), "r"(a.w), "r"(b.x), "r"(b.y));
}
__device__ __forceinline__ uint64_t dup2(float x) {
    uint64_t r;
    asm("mov.b64 %0, {%1, %1};" : "=l"(r) : "f"(x));
    return r;
}
__device__ __forceinline__ uint64_t fma2(uint64_t a, uint64_t b, uint64_t c) {
    uint64_t d;
    asm("fma.rn.f32x2 %0, %1, %2, %3;" : "=l"(d) : "l"(a), "l"(b), "l"(c));
    return d;
}

// ---------------------------------------------------------- prep kernel -----
__global__ void prep_w_kernel(const float* __restrict__ filters) {
    int idx  = blockIdx.x * 256 + threadIdx.x;    // 8192 total
    int i    = (idx >> 7) & 63;
    int t    = (idx >> 5) & 3;
    int lane = idx & 31;
    int gid = lane >> 2, q = lane & 3;
    int k0 = t * 16 + q * 2;
    int l0 = gid, l1 = gid + 8;

    float e[8];
    int ls[8] = {l0, l0, l1, l1, l0, l0, l1, l1};
    int ks[8] = {k0, k0 + 1, k0, k0 + 1, k0 + 8, k0 + 9, k0 + 8, k0 + 9};
    #pragma unroll
    for (int j = 0; j < 8; ++j)
        e[j] = filters[(i * 64 + ks[j]) * 16 + ls[j]];

    g_Wfrag[idx] = make_uint4(pack_half2(e[0], e[1]), pack_half2(e[2], e[3]),
                              pack_half2(e[4], e[5]), pack_half2(e[6], e[7]));
}

// ------------------------------------------------------------ main kernel ---
// SMEM: x0h 56*224 u32 (50176B rounded region 57344) | x1r 14*1024 f32 |
//       ws 8*1024 f32 | x0f 8*224 f32
static constexpr int SM_X0H = 0;            // 56*224*4 = 50176 (pad to 57344)
static constexpr int SM_X1R = 57344;        // 57344
static constexpr int SM_WS  = 114688;       // 32768
static constexpr int SM_X0F = 147456;       // 7168
static constexpr int SMEM_TOTAL = 154624;
// overlays (after mainloop): wb on x0h (56 bufs * 136 f), wb2 on ws (2*224*16 f)
static constexpr int SM_WB  = SM_X0H;
static constexpr int SM_WB2 = SM_WS;

__global__ __launch_bounds__(384, 1) void fm_main_kernel(
    const float* __restrict__ x0g,
    const float* __restrict__ x1g,
    const float* __restrict__ filters,
    float* __restrict__ outg)
{
    extern __shared__ __align__(16) unsigned char smem[];
    uint32_t* x0h = (uint32_t*)(smem + SM_X0H);
    float*    x1r = (float*)(smem + SM_X1R);
    float*    ws  = (float*)(smem + SM_WS);
    float*    x0f = (float*)(smem + SM_X0F);
    float*    wb  = (float*)(smem + SM_WB);
    float*    wb2 = (float*)(smem + SM_WB2);

    int tid = threadIdx.x;
    int w = tid >> 5, lane = tid & 31;
    int gid = lane >> 2, q = lane & 3;
    int bid = blockIdx.x;
    int nb    = (bid < 124) ? 14 : 13;
    int bbase = (bid < 124) ? bid * 14 : 1736 + (bid - 124) * 13;
    int nm = nb * 16;           // real m rows (208 or 224)
    int mcmax = 2 * nb - 1;     // last real mc chunk

    // ---- stage: x1r, x0h (fp16-dup, i<56), x0f (f32, i>=56), ws ----
    {
        const float4* src = (const float4*)(x1g + (size_t)bbase * 1024);
        float4* dst = (float4*)x1r;
        for (int e = tid; e < nb * 256; e += 384) dst[e] = src[e];
        const float4* fsrc = (const float4*)(filters + NHI * 1024);
        float4* wsd = (float4*)ws;
        for (int e = tid; e < 2048; e += 384) wsd[e] = fsrc[e];
        const float* x0p = x0g + (size_t)bbase * 1024;
        for (int e = tid; e < nb * 1024; e += 384) {
            int bl = e >> 10, r = e & 1023;
            int i = r >> 4, d = r & 15;
            int m = bl * 16 + d;
            float v = x0p[e];
            if (i < NHI) {
                __half hh = __float2half(v);
                x0h[i * MMAX + m] = (uint32_t)(*(unsigned short*)&hh) * 0x00010001u;
            } else {
                x0f[(i - NHI) * MMAX + m] = v;
            }
        }
    }
    __syncthreads();

    if (w < 8) {
        // ================= HMMA warps: (Q = w&3, h = w>>2) =================
        int Q = w & 3, h = w >> 2;

        // chunk offsets (clamped for nb=13 -> duplicate-garbage, discarded)
        int moff[7];
        #pragma unroll
        for (int mcl = 0; mcl < 7; ++mcl) {
            int mc = Q * 7 + mcl;
            if (mc > mcmax) mc = mcmax;
            moff[mcl] = mc * 8 + gid;
        }

        // register B fragments from x1r
        uint2 Bf[7][4];
        #pragma unroll
        for (int mcl = 0; mcl < 7; ++mcl) {
            int r = moff[mcl];
            const float* base = x1r + (r >> 4) * 1024 + (r & 15);
            #pragma unroll
            for (int t = 0; t < 4; ++t) {
                int k0 = t * 16 + q * 2;
                Bf[mcl][t] = make_uint2(
                    pack_half2(base[k0 * 16], base[(k0 + 1) * 16]),
                    pack_half2(base[(k0 + 8) * 16], base[(k0 + 9) * 16]));
            }
        }

        float acc[7][4];
        #pragma unroll
        for (int mcl = 0; mcl < 7; ++mcl)
            #pragma unroll
            for (int r = 0; r < 4; ++r) acc[mcl][r] = 0.0f;

        const uint4* wp = g_Wfrag + lane;
        int i0 = h * 28;
        uint4 Wc[4], Wn[4];
        #pragma unroll
        for (int t = 0; t < 4; ++t) Wc[t] = wp[(i0 * 4 + t) * 32];

        for (int il = 0; il < 28; ++il) {
            int i = i0 + il;
            if (il < 27) {
                #pragma unroll
                for (int t = 0; t < 4; ++t) Wn[t] = wp[((i + 1) * 4 + t) * 32];
            }
            const uint32_t* x0row = x0h + i * MMAX;
            #pragma unroll
            for (int mcl = 0; mcl < 7; ++mcl) {
                uint32_t xh = x0row[moff[mcl]];
                #pragma unroll
                for (int t = 0; t < 4; ++t) {
                    uint2 bs = make_uint2(hmul2(Bf[mcl][t].x, xh),
                                          hmul2(Bf[mcl][t].y, xh));
                    mma16816(acc[mcl], Wc[t], bs);
                }
            }
            #pragma unroll
            for (int t = 0; t < 4; ++t) Wc[t] = Wn[t];
        }

        __syncthreads();   // staging reads done everywhere; overlays safe

        // partial writeback: wb[(w*7+mcl)*136 + l*8 + m_in_chunk]
        #pragma unroll
        for (int mcl = 0; mcl < 7; ++mcl) {
            float* bptr = wb + (w * 7 + mcl) * 136;
            *(float2*)&bptr[gid * 8 + 2 * q]       = make_float2(acc[mcl][0], acc[mcl][1]);
            *(float2*)&bptr[(gid + 8) * 8 + 2 * q] = make_float2(acc[mcl][2], acc[mcl][3]);
        }
    } else {
        // ================= scalar warps: (ip = sw>>1, lh = sw&1) ============
        int sw = w - 8;
        int ip = sw >> 1;      // i in [56+ip*4, 56+ip*4+4)
        int lh = sw & 1;       // l in [lh*8, lh*8+8)

        // 7 m's per thread: m = lane + 32*mi
        int boff[7];
        #pragma unroll
        for (int mi = 0; mi < 7; ++mi) {
            int m = lane + mi * 32;
            boff[mi] = (m >> 4) * 1024 + (m & 15);
        }

        uint64_t a2[7][4];
        #pragma unroll
        for (int mi = 0; mi < 7; ++mi)
            #pragma unroll
            for (int lp = 0; lp < 4; ++lp) a2[mi][lp] = 0ull;

        for (int ii = 0; ii < 4; ++ii) {
            int isl = ip * 4 + ii;
            float x0c[7];
            #pragma unroll
            for (int mi = 0; mi < 7; ++mi)
                x0c[mi] = x0f[isl * MMAX + lane + mi * 32];
            const float* wrow = ws + isl * 1024 + lh * 8;
            #pragma unroll 2
            for (int j = 0; j < 64; ++j) {
                ulonglong2 w0 = *(const ulonglong2*)(wrow + j * 16);
                ulonglong2 w1 = *(const ulonglong2*)(wrow + j * 16 + 4);
                #pragma unroll
                for (int mi = 0; mi < 7; ++mi) {
                    uint64_t pd = dup2(x0c[mi] * x1r[boff[mi] + j * 16]);
                    a2[mi][0] = fma2(w0.x, pd, a2[mi][0]);
                    a2[mi][1] = fma2(w0.y, pd, a2[mi][1]);
                    a2[mi][2] = fma2(w1.x, pd, a2[mi][2]);
                    a2[mi][3] = fma2(w1.y, pd, a2[mi][3]);
                }
            }
        }

        __syncthreads();   // matches hmma warps' barrier

        // scalar partials: wb2[ip*3584 + m*16 + lh*8 + ...]
        #pragma unroll
        for (int mi = 0; mi < 7; ++mi) {
            int m = lane + mi * 32;
            float* dst = wb2 + ip * 3584 + m * 16 + lh * 8;
            #pragma unroll
            for (int lp = 0; lp < 4; ++lp)
                *(uint64_t*)&dst[lp * 2] = a2[mi][lp];
        }
    }
    __syncthreads();

    // ---- final reduce: 2 hmma h-halves + 2 scalar ip slices; coalesced ----
    for (int o = tid; o < nb * 256; o += 384) {
        int bl = o >> 8, l = (o >> 4) & 15, d = o & 15;
        int m = bl * 16 + d;
        int mc = m >> 3;
        int Q = (mc * 9363) >> 16;     // mc / 7 for mc < 28
        int mcl = mc - Q * 7;
        int e = mcl * 136 + l * 8 + (m & 7);
        float s = wb[(Q * 7) * 136 + e] + wb[((4 + Q) * 7) * 136 + e];
        s += wb2[m * 16 + l] + wb2[3584 + m * 16 + l];
        outg[(size_t)(bbase + bl) * 256 + l * 16 + d] = s;
    }
}

// ------------------------------------------------------------------ launch --
extern "C" void kernel_launch(void* const* d_in, const int* in_sizes, int n_in,
                              void* d_out, int out_size) {
    const float* x0 = (const float*)d_in[0];
    const float* x1 = (const float*)d_in[1];
    const float* filters = (const float*)d_in[2];
    float* out = (float*)d_out;

    cudaFuncSetAttribute(fm_main_kernel,
                         cudaFuncAttributeMaxDynamicSharedMemorySize, SMEM_TOTAL);

    prep_w_kernel<<<32, 256>>>(filters);
    fm_main_kernel<<<148, 384, SMEM_TOTAL>>>(x0, x1, filters, out);
}